// round 8
// baseline (speedup 1.0000x reference)
#include <cuda_runtime.h>
#include <cstdint>

#define NB    4
#define NPIX  65536     // 256*256
#define CCH   128
#define HF    512
#define WF    512
#define NPTS  8192
#define HID   256
#define NFEAT 129
#define TILE  128       // points per block in main kernel

// ---------------- device scratch (no allocations allowed) ----------------
__device__ unsigned long long g_thresh[NB];
__device__ unsigned long long g_prefix[NB];
__device__ int g_target[NB];
__device__ int g_cnt[NB];
__device__ int g_idx[NB * NPTS];
__device__ unsigned int g_hist[NB * 65536];   // zero at load; scans re-zero

// 48-bit key: (|v| bits << 16) | idx  -> unique, lexicographic (|v|, idx)
// matches jax top_k(-|v|) selection set including stable tie-break.
__device__ __forceinline__ unsigned long long make_key(float v, int i) {
    unsigned int a = __float_as_uint(v) & 0x7fffffffu;
    return (((unsigned long long)a) << 16) | (unsigned int)i;
}

// ---------------- kernel 0: per-call state reset -------------------------
__global__ void init_kernel() {
    int b = threadIdx.x;
    if (b < NB) { g_prefix[b] = 0ull; g_target[b] = NPTS - 1; g_cnt[b] = 0; }
}

// ---------------- kernel 1a: 16-bit radix histogram (wide) ---------------
// grid (32, NB) x 256 threads; 8 elems/thread, coalesced.
__global__ void hist_kernel(const float* __restrict__ coarse, int shift) {
    const int b   = blockIdx.y;
    const int tid = threadIdx.x;
    const unsigned long long pref = g_prefix[b];
    const float* src = coarse + b * NPIX;
    unsigned int* hist = g_hist + b * 65536;
    const int base = blockIdx.x * 2048;
    #pragma unroll
    for (int j = 0; j < 8; j++) {
        const int i = base + j * 256 + tid;
        unsigned long long k = make_key(src[i], i);
        if ((k >> (shift + 16)) == pref)
            atomicAdd(&hist[(unsigned int)(k >> shift) & 0xffffu], 1u);
    }
}

// ---------------- kernel 1b: scan 64K bins, locate target, zero hist -----
// grid NB x 1024 threads.
__global__ void scan_kernel(int is_last) {
    __shared__ unsigned int ssum[1024];
    const int b   = blockIdx.x;
    const int tid = threadIdx.x;
    unsigned int* hist = g_hist + b * 65536;

    unsigned int s = 0;
    const int base = tid * 64;
    for (int i = 0; i < 64; i++) s += hist[base + i];
    ssum[tid] = s;
    __syncthreads();
    // Hillis-Steele inclusive scan
    for (int off = 1; off < 1024; off <<= 1) {
        unsigned int v = (tid >= off) ? ssum[tid - off] : 0u;
        __syncthreads();
        ssum[tid] += v;
        __syncthreads();
    }
    const unsigned int incl = ssum[tid];
    const unsigned int excl = incl - s;
    const unsigned int target = (unsigned int)g_target[b];
    if (target >= excl && target < incl) {           // unique owner thread
        unsigned int rem = target - excl;
        int bin = base;
        for (int i = 0; i < 64; i++) {
            unsigned int h = hist[bin];
            if (rem < h) break;
            rem -= h; bin++;
        }
        unsigned long long np = (g_prefix[b] << 16) | (unsigned int)(bin & 0xffff);
        if (is_last) {
            g_thresh[b] = np;                        // full 48-bit key
        } else {
            g_prefix[b] = np;
            g_target[b] = (int)rem;
        }
    }
    __syncthreads();
    // re-zero for next pass / next graph replay
    for (int i = tid; i < 65536; i += 1024) hist[i] = 0u;
}

// ---------------- kernel 2: warp-aggregated compaction -------------------
__global__ void compact_kernel(const float* __restrict__ coarse) {
    const int i = blockIdx.x * blockDim.x + threadIdx.x;   // 0..262143
    const int b  = i >> 16;
    const int li = i & 0xffff;
    unsigned long long k = make_key(coarse[i], li);
    const bool take = (k <= g_thresh[b]);
    // warps never straddle a batch (65536 % 32 == 0)
    unsigned mask = __ballot_sync(0xffffffffu, take);
    if (take) {
        const int lane = threadIdx.x & 31;
        const int leader = __ffs(mask) - 1;
        int pos = 0;
        if (lane == leader) pos = atomicAdd(&g_cnt[b], __popc(mask));
        pos = __shfl_sync(0xffffffffu, pos, leader);
        pos += __popc(mask & ((1u << lane) - 1u));
        g_idx[b * NPTS + pos] = li;
    }
}

// ---------------- kernel 3: sample + MLP + scatter ------------------------
// grid (NPTS/TILE, NB), 512 threads, dynamic smem:
//   sW1  : 129*256 floats (staged W1)
//   sF   : 129*128 floats (feats, f-major)
//   sPart: 32*128 floats  (partial W2 dots for deterministic reduce)
//   sIdx : 128 ints
#define SMEM_FLOATS (NFEAT * HID + NFEAT * TILE + 32 * TILE)
#define SMEM_BYTES  (SMEM_FLOATS * 4 + TILE * 4)

extern __shared__ float smem[];

__global__ __launch_bounds__(512, 1) void main_kernel(
    const float* __restrict__ coarse, const float* __restrict__ fine,
    const float* __restrict__ W1, const float* __restrict__ b1,
    const float* __restrict__ W2, const float* __restrict__ b2,
    float* __restrict__ out)
{
    float* sW1   = smem;                       // 33024 floats
    float* sF    = sW1 + NFEAT * HID;          // 16512
    float* sPart = sF + NFEAT * TILE;          // 4096
    int*   sIdx  = (int*)(sPart + 32 * TILE);  // 128

    const int tid   = threadIdx.x;
    const int batch = blockIdx.y;
    const int tile  = blockIdx.x;

    for (int i = tid; i < NFEAT * HID; i += 512) sW1[i] = W1[i];
    if (tid < TILE) sIdx[tid] = g_idx[batch * NPTS + tile * TILE + tid];
    __syncthreads();

    // ---- sampling: bilinear == 0.25 * (2x2 block at (2r, 2c)) ----
    const float* fbase = fine + (size_t)batch * CCH * HF * WF;
    #pragma unroll 4
    for (int w = tid; w < CCH * TILE; w += 512) {
        const int p  = w & (TILE - 1);
        const int ch = w >> 7;
        const int idx = sIdx[p];
        const int y0 = (idx >> 8) * 2;
        const int x0 = (idx & 255) * 2;
        const float* ptr = fbase + ((size_t)ch * HF + y0) * WF + x0;
        float2 r0 = *(const float2*)ptr;
        float2 r1 = *(const float2*)(ptr + WF);
        sF[ch * TILE + p] = 0.25f * ((r0.x + r0.y) + (r1.x + r1.y));
    }
    if (tid < TILE) sF[CCH * TILE + tid] = coarse[batch * NPIX + sIdx[tid]];
    __syncthreads();

    // ---- register-blocked fp32 GEMM: hid[256 x 128] ----
    const int hg = tid & 31;       // hidden group (32 groups of 8)
    const int pg = tid >> 5;       // point group  (16 groups of 8)
    const int h0 = hg * 8;
    const int p0 = pg * 8;

    float acc[8][8];
    #pragma unroll
    for (int i = 0; i < 8; i++)
        #pragma unroll
        for (int j = 0; j < 8; j++) acc[i][j] = 0.0f;

    for (int f = 0; f < NFEAT; f++) {
        float4 wa = *(const float4*)&sW1[f * HID + h0];
        float4 wb = *(const float4*)&sW1[f * HID + h0 + 4];
        float4 xa = *(const float4*)&sF[f * TILE + p0];
        float4 xb = *(const float4*)&sF[f * TILE + p0 + 4];
        float w[8] = {wa.x, wa.y, wa.z, wa.w, wb.x, wb.y, wb.z, wb.w};
        float x[8] = {xa.x, xa.y, xa.z, xa.w, xb.x, xb.y, xb.z, xb.w};
        #pragma unroll
        for (int i = 0; i < 8; i++)
            #pragma unroll
            for (int j = 0; j < 8; j++)
                acc[i][j] += w[i] * x[j];
    }

    // ---- epilogue: relu + W2 dot (partial per hidden-group) ----
    float part[8];
    #pragma unroll
    for (int j = 0; j < 8; j++) part[j] = 0.0f;
    #pragma unroll
    for (int i = 0; i < 8; i++) {
        const int h = h0 + i;
        const float b1v = b1[h];
        const float w2v = W2[h];
        #pragma unroll
        for (int j = 0; j < 8; j++)
            part[j] += fmaxf(acc[i][j] + b1v, 0.0f) * w2v;
    }
    #pragma unroll
    for (int j = 0; j < 8; j++)
        sPart[hg * TILE + p0 + j] = part[j];   // unique slot per (hg, point)
    __syncthreads();

    // ---- deterministic reduce over 32 hidden-groups + scatter ----
    if (tid < TILE) {
        float r = b2[0];
        #pragma unroll
        for (int g = 0; g < 32; g++) r += sPart[g * TILE + tid];
        out[batch * NPIX + sIdx[tid]] = r;
    }
}

// ---------------- launch ---------------------------------------------------
extern "C" void kernel_launch(void* const* d_in, const int* in_sizes, int n_in,
                              void* d_out, int out_size) {
    const float* coarse = (const float*)d_in[0];
    const float* fine   = (const float*)d_in[1];
    const float* W1     = (const float*)d_in[2];
    const float* b1     = (const float*)d_in[3];
    const float* W2     = (const float*)d_in[4];
    const float* b2     = (const float*)d_in[5];
    float* out = (float*)d_out;

    // out = coarse everywhere; refined points overwritten by main_kernel
    cudaMemcpyAsync(out, coarse, (size_t)NB * NPIX * sizeof(float),
                    cudaMemcpyDeviceToDevice, 0);

    init_kernel<<<1, 32>>>();

    // 3-pass 16-bit radix select of the rank-8191 48-bit key
    hist_kernel<<<dim3(32, NB), 256>>>(coarse, 32);
    scan_kernel<<<NB, 1024>>>(0);
    hist_kernel<<<dim3(32, NB), 256>>>(coarse, 16);
    scan_kernel<<<NB, 1024>>>(0);
    hist_kernel<<<dim3(32, NB), 256>>>(coarse, 0);
    scan_kernel<<<NB, 1024>>>(1);

    compact_kernel<<<(NB * NPIX) / 256, 256>>>(coarse);

    cudaFuncSetAttribute(main_kernel,
                         cudaFuncAttributeMaxDynamicSharedMemorySize,
                         SMEM_BYTES);
    main_kernel<<<dim3(NPTS / TILE, NB), 512, SMEM_BYTES>>>(
        coarse, fine, W1, b1, W2, b2, out);
}

// round 9
// speedup vs baseline: 1.5455x; 1.5455x over previous
#include <cuda_runtime.h>
#include <cstdint>

#define NB    4
#define NPIX  65536     // 256*256
#define CCH   128
#define HF    512
#define WF    512
#define NPTS  8192
#define HID   256
#define NFEAT 129
#define TILE  128       // points per block in main kernel
#define NBIN  4096      // 12-bit radix digit

// ---------------- device scratch (no allocations allowed) ----------------
__device__ unsigned long long g_thresh[NB];
__device__ unsigned long long g_prefix[NB];
__device__ int g_target[NB];
__device__ int g_cnt[NB];
__device__ int g_idx[NB * NPTS];
__device__ unsigned int g_hist[NB * NBIN];   // zero at load; scans re-zero

// 48-bit key: (|v| bits << 16) | idx  -> unique, lexicographic (|v|, idx)
// matches jax top_k(-|v|) selection set including stable tie-break.
__device__ __forceinline__ unsigned long long make_key(float v, int i) {
    unsigned int a = __float_as_uint(v) & 0x7fffffffu;
    return (((unsigned long long)a) << 16) | (unsigned int)i;
}

// ---------------- kernel 0: per-call state reset -------------------------
__global__ void init_kernel() {
    int b = threadIdx.x;
    if (b < NB) { g_prefix[b] = 0ull; g_target[b] = NPTS - 1; g_cnt[b] = 0; }
}

// ---------------- kernel 1a: 12-bit radix histogram (smem-staged) --------
// grid (32, NB) x 256 threads; 8 elems/thread, coalesced.
__global__ void hist_kernel(const float* __restrict__ coarse, int shift) {
    __shared__ unsigned int s_hist[NBIN];
    const int b   = blockIdx.y;
    const int tid = threadIdx.x;
    for (int i = tid; i < NBIN; i += 256) s_hist[i] = 0u;
    __syncthreads();

    const unsigned long long pref = g_prefix[b];
    const float* src = coarse + b * NPIX;
    const int base = blockIdx.x * 2048;
    #pragma unroll
    for (int j = 0; j < 8; j++) {
        const int i = base + j * 256 + tid;
        unsigned long long k = make_key(src[i], i);
        if ((k >> (shift + 12)) == pref)
            atomicAdd(&s_hist[(unsigned int)(k >> shift) & 0xfffu], 1u);
    }
    __syncthreads();

    unsigned int* hist = g_hist + b * NBIN;
    for (int i = tid; i < NBIN; i += 256) {
        unsigned int v = s_hist[i];
        if (v) atomicAdd(&hist[i], v);
    }
}

// ---------------- kernel 1b: scan 4096 bins, locate target, zero hist ----
// grid NB x 1024 threads; uint4-vectorized bin access.
__global__ void scan_kernel(int is_last) {
    __shared__ unsigned int ssum[1024];
    const int b   = blockIdx.x;
    const int tid = threadIdx.x;
    uint4* hist4 = reinterpret_cast<uint4*>(g_hist + b * NBIN);

    const uint4 h = hist4[tid];                      // bins 4*tid .. 4*tid+3
    const unsigned int s = h.x + h.y + h.z + h.w;
    ssum[tid] = s;
    __syncthreads();
    // Hillis-Steele inclusive scan over 1024 partials
    for (int off = 1; off < 1024; off <<= 1) {
        unsigned int v = (tid >= off) ? ssum[tid - off] : 0u;
        __syncthreads();
        ssum[tid] += v;
        __syncthreads();
    }
    const unsigned int incl = ssum[tid];
    const unsigned int excl = incl - s;
    const unsigned int target = (unsigned int)g_target[b];
    if (target >= excl && target < incl) {           // unique owner thread
        unsigned int rem = target - excl;
        int bin = tid * 4;
        unsigned int hv[4] = {h.x, h.y, h.z, h.w};
        #pragma unroll
        for (int i = 0; i < 4; i++) {
            if (rem < hv[i]) break;
            rem -= hv[i]; bin++;
        }
        unsigned long long np = (g_prefix[b] << 12) | (unsigned int)(bin & 0xfff);
        if (is_last) {
            g_thresh[b] = np;                        // full 48-bit key
        } else {
            g_prefix[b] = np;
            g_target[b] = (int)rem;
        }
    }
    // re-zero for next pass / next graph replay
    hist4[tid] = make_uint4(0u, 0u, 0u, 0u);
}

// ---------------- kernel 2: warp-aggregated compaction -------------------
__global__ void compact_kernel(const float* __restrict__ coarse) {
    const int i = blockIdx.x * blockDim.x + threadIdx.x;   // 0..262143
    const int b  = i >> 16;
    const int li = i & 0xffff;
    unsigned long long k = make_key(coarse[i], li);
    const bool take = (k <= g_thresh[b]);
    // warps never straddle a batch (65536 % 32 == 0)
    unsigned mask = __ballot_sync(0xffffffffu, take);
    if (take) {
        const int lane = threadIdx.x & 31;
        const int leader = __ffs(mask) - 1;
        int pos = 0;
        if (lane == leader) pos = atomicAdd(&g_cnt[b], __popc(mask));
        pos = __shfl_sync(0xffffffffu, pos, leader);
        pos += __popc(mask & ((1u << lane) - 1u));
        g_idx[b * NPTS + pos] = li;
    }
}

// ---------------- kernel 3: sample + MLP + scatter ------------------------
// grid (NPTS/TILE, NB), 512 threads, dynamic smem:
//   sW1  : 129*256 floats (staged W1)
//   sF   : 129*128 floats (feats, f-major)
//   sPart: 32*128 floats  (partial W2 dots for deterministic reduce)
//   sIdx : 128 ints
#define SMEM_FLOATS (NFEAT * HID + NFEAT * TILE + 32 * TILE)
#define SMEM_BYTES  (SMEM_FLOATS * 4 + TILE * 4)

extern __shared__ float smem[];

__global__ __launch_bounds__(512, 1) void main_kernel(
    const float* __restrict__ coarse, const float* __restrict__ fine,
    const float* __restrict__ W1, const float* __restrict__ b1,
    const float* __restrict__ W2, const float* __restrict__ b2,
    float* __restrict__ out)
{
    float* sW1   = smem;                       // 33024 floats
    float* sF    = sW1 + NFEAT * HID;          // 16512
    float* sPart = sF + NFEAT * TILE;          // 4096
    int*   sIdx  = (int*)(sPart + 32 * TILE);  // 128

    const int tid   = threadIdx.x;
    const int batch = blockIdx.y;
    const int tile  = blockIdx.x;

    for (int i = tid; i < NFEAT * HID; i += 512) sW1[i] = W1[i];
    if (tid < TILE) sIdx[tid] = g_idx[batch * NPTS + tile * TILE + tid];
    __syncthreads();

    // ---- sampling: bilinear == 0.25 * (2x2 block at (2r, 2c)) ----
    const float* fbase = fine + (size_t)batch * CCH * HF * WF;
    #pragma unroll 4
    for (int w = tid; w < CCH * TILE; w += 512) {
        const int p  = w & (TILE - 1);
        const int ch = w >> 7;
        const int idx = sIdx[p];
        const int y0 = (idx >> 8) * 2;
        const int x0 = (idx & 255) * 2;
        const float* ptr = fbase + ((size_t)ch * HF + y0) * WF + x0;
        float2 r0 = *(const float2*)ptr;
        float2 r1 = *(const float2*)(ptr + WF);
        sF[ch * TILE + p] = 0.25f * ((r0.x + r0.y) + (r1.x + r1.y));
    }
    if (tid < TILE) sF[CCH * TILE + tid] = coarse[batch * NPIX + sIdx[tid]];
    __syncthreads();

    // ---- register-blocked fp32 GEMM: hid[256 x 128] ----
    const int hg = tid & 31;       // hidden group (32 groups of 8)
    const int pg = tid >> 5;       // point group  (16 groups of 8)
    const int h0 = hg * 8;
    const int p0 = pg * 8;

    float acc[8][8];
    #pragma unroll
    for (int i = 0; i < 8; i++)
        #pragma unroll
        for (int j = 0; j < 8; j++) acc[i][j] = 0.0f;

    for (int f = 0; f < NFEAT; f++) {
        float4 wa = *(const float4*)&sW1[f * HID + h0];
        float4 wb = *(const float4*)&sW1[f * HID + h0 + 4];
        float4 xa = *(const float4*)&sF[f * TILE + p0];
        float4 xb = *(const float4*)&sF[f * TILE + p0 + 4];
        float w[8] = {wa.x, wa.y, wa.z, wa.w, wb.x, wb.y, wb.z, wb.w};
        float x[8] = {xa.x, xa.y, xa.z, xa.w, xb.x, xb.y, xb.z, xb.w};
        #pragma unroll
        for (int i = 0; i < 8; i++)
            #pragma unroll
            for (int j = 0; j < 8; j++)
                acc[i][j] += w[i] * x[j];
    }

    // ---- epilogue: relu + W2 dot (partial per hidden-group) ----
    float part[8];
    #pragma unroll
    for (int j = 0; j < 8; j++) part[j] = 0.0f;
    #pragma unroll
    for (int i = 0; i < 8; i++) {
        const int h = h0 + i;
        const float b1v = b1[h];
        const float w2v = W2[h];
        #pragma unroll
        for (int j = 0; j < 8; j++)
            part[j] += fmaxf(acc[i][j] + b1v, 0.0f) * w2v;
    }
    #pragma unroll
    for (int j = 0; j < 8; j++)
        sPart[hg * TILE + p0 + j] = part[j];   // unique slot per (hg, point)
    __syncthreads();

    // ---- deterministic reduce over 32 hidden-groups + scatter ----
    if (tid < TILE) {
        float r = b2[0];
        #pragma unroll
        for (int g = 0; g < 32; g++) r += sPart[g * TILE + tid];
        out[batch * NPIX + sIdx[tid]] = r;
    }
}

// ---------------- launch ---------------------------------------------------
extern "C" void kernel_launch(void* const* d_in, const int* in_sizes, int n_in,
                              void* d_out, int out_size) {
    const float* coarse = (const float*)d_in[0];
    const float* fine   = (const float*)d_in[1];
    const float* W1     = (const float*)d_in[2];
    const float* b1     = (const float*)d_in[3];
    const float* W2     = (const float*)d_in[4];
    const float* b2     = (const float*)d_in[5];
    float* out = (float*)d_out;

    // out = coarse everywhere; refined points overwritten by main_kernel
    cudaMemcpyAsync(out, coarse, (size_t)NB * NPIX * sizeof(float),
                    cudaMemcpyDeviceToDevice, 0);

    init_kernel<<<1, 32>>>();

    // 4-pass 12-bit radix select of the rank-8191 48-bit key
    hist_kernel<<<dim3(32, NB), 256>>>(coarse, 36);
    scan_kernel<<<NB, 1024>>>(0);
    hist_kernel<<<dim3(32, NB), 256>>>(coarse, 24);
    scan_kernel<<<NB, 1024>>>(0);
    hist_kernel<<<dim3(32, NB), 256>>>(coarse, 12);
    scan_kernel<<<NB, 1024>>>(0);
    hist_kernel<<<dim3(32, NB), 256>>>(coarse, 0);
    scan_kernel<<<NB, 1024>>>(1);

    compact_kernel<<<(NB * NPIX) / 256, 256>>>(coarse);

    cudaFuncSetAttribute(main_kernel,
                         cudaFuncAttributeMaxDynamicSharedMemorySize,
                         SMEM_BYTES);
    main_kernel<<<dim3(NPTS / TILE, NB), 512, SMEM_BYTES>>>(
        coarse, fine, W1, b1, W2, b2, out);
}